// round 2
// baseline (speedup 1.0000x reference)
#include <cuda_runtime.h>
#include <cstdint>

// Problem constants (fixed by the reference)
#define NN 50000
#define EE 800000
#define CC 128   // channels in = out

// Scratch (static __device__ arrays — allocation-free per harness rules)
__device__ float g_hs[(size_t)NN * CC];   // hs[j] = (x@W)[j] * dinv[j]
__device__ float g_dinv[NN];
__device__ int   g_deg[NN];

// ---------------------------------------------------------------------------
// 1) deg init: every node has its self loop -> deg starts at 1
__global__ void deg_init_kernel() {
    int i = blockIdx.x * blockDim.x + threadIdx.x;
    if (i < NN) g_deg[i] = 1;
}

// 2) deg count: one thread per edge, count at dst (PyG gcn_norm uses col).
//    edge_index is INT32 (JAX x64-disabled downcasts the int64 request).
__global__ void deg_count_kernel(const int* __restrict__ ei) {
    int e = blockIdx.x * blockDim.x + threadIdx.x;
    if (e < EE) {
        int dst = ei[EE + e];
        atomicAdd(&g_deg[dst], 1);
    }
}

// 3) dinv = rsqrt(deg)   (deg >= 1 always, so no zero-guard needed)
__global__ void dinv_kernel() {
    int i = blockIdx.x * blockDim.x + threadIdx.x;
    if (i < NN) g_dinv[i] = rsqrtf((float)g_deg[i]);
}

// ---------------------------------------------------------------------------
// 4) GEMM: hs = (x @ W) * dinv[row]; also seed out = hs (self-loop message).
//    Block: 256 threads, 32 rows per block.
//    Thread (lane = t&31, rg = t>>5): 4 cols (lane*4..) x 4 rows (rg*4..)
__global__ void gemm_kernel(const float* __restrict__ x,
                            const float* __restrict__ w,
                            float* __restrict__ out) {
    __shared__ float sx[32][CC];
    const int row0 = blockIdx.x * 32;
    const int t = threadIdx.x;
    const int lane = t & 31;
    const int rg = t >> 5;

    // cooperative load of 32 x-rows (zero-pad past N)
    for (int i = t; i < 32 * 32; i += 256) {           // 1024 float4s
        int r = i >> 5;
        int c4 = i & 31;
        int row = row0 + r;
        float4 v = make_float4(0.f, 0.f, 0.f, 0.f);
        if (row < NN) v = ((const float4*)x)[(size_t)row * 32 + c4];
        ((float4*)&sx[r][0])[c4] = v;
    }
    __syncthreads();

    float acc[4][4] = {};
    const int r0 = rg * 4;

#pragma unroll 4
    for (int k = 0; k < CC; k++) {
        float4 wv = ((const float4*)w)[k * 32 + lane];  // coalesced, L1-resident
        float x0 = sx[r0 + 0][k];   // broadcast (conflict-free)
        float x1 = sx[r0 + 1][k];
        float x2 = sx[r0 + 2][k];
        float x3 = sx[r0 + 3][k];
        acc[0][0] += x0 * wv.x; acc[0][1] += x0 * wv.y; acc[0][2] += x0 * wv.z; acc[0][3] += x0 * wv.w;
        acc[1][0] += x1 * wv.x; acc[1][1] += x1 * wv.y; acc[1][2] += x1 * wv.z; acc[1][3] += x1 * wv.w;
        acc[2][0] += x2 * wv.x; acc[2][1] += x2 * wv.y; acc[2][2] += x2 * wv.z; acc[2][3] += x2 * wv.w;
        acc[3][0] += x3 * wv.x; acc[3][1] += x3 * wv.y; acc[3][2] += x3 * wv.z; acc[3][3] += x3 * wv.w;
    }

#pragma unroll
    for (int r = 0; r < 4; r++) {
        int row = row0 + r0 + r;
        if (row < NN) {
            float d = g_dinv[row];
            float4 v = make_float4(acc[r][0] * d, acc[r][1] * d,
                                   acc[r][2] * d, acc[r][3] * d);
            ((float4*)g_hs)[(size_t)row * 32 + lane] = v;
            ((float4*)out)[(size_t)row * 32 + lane] = v;  // seed with self-loop msg
        }
    }
}

// ---------------------------------------------------------------------------
// 5) Edge scatter: one warp per edge. 32 lanes x float4 = full 128-ch row.
//    Gather hs[src] (L2-resident), scatter-add into out[dst] via a single
//    vectorized red.global.add.v4.f32 per lane (sm_90+; 4x fewer RED ops
//    than scalar atomicAdd).
__global__ void scatter_kernel(const int* __restrict__ ei,
                               float* __restrict__ out) {
    long long gid = (long long)blockIdx.x * blockDim.x + threadIdx.x;
    int e = (int)(gid >> 5);
    if (e >= EE) return;
    int lane = threadIdx.x & 31;

    int src = __ldg(&ei[e]);
    int dst = __ldg(&ei[EE + e]);

    float4 v = __ldg(((const float4*)g_hs) + (size_t)src * 32 + lane);
    float* o = out + (size_t)dst * CC + lane * 4;
    asm volatile("red.global.add.v4.f32 [%0], {%1, %2, %3, %4};"
                 :: "l"(o), "f"(v.x), "f"(v.y), "f"(v.z), "f"(v.w)
                 : "memory");
}

// ---------------------------------------------------------------------------
// 6) Finalize: out = relu(out * dinv[row] + bias)
__global__ void finalize_kernel(float* __restrict__ out,
                                const float* __restrict__ bias) {
    int i = blockIdx.x * blockDim.x + threadIdx.x;  // over N*32 float4s
    if (i >= NN * 32) return;
    int row = i >> 5;
    int c4 = i & 31;
    float d = g_dinv[row];
    float4 b = ((const float4*)bias)[c4];
    float4 v = ((float4*)out)[i];
    v.x = fmaxf(fmaf(v.x, d, b.x), 0.f);
    v.y = fmaxf(fmaf(v.y, d, b.y), 0.f);
    v.z = fmaxf(fmaf(v.z, d, b.z), 0.f);
    v.w = fmaxf(fmaf(v.w, d, b.w), 0.f);
    ((float4*)out)[i] = v;
}

// ---------------------------------------------------------------------------
extern "C" void kernel_launch(void* const* d_in, const int* in_sizes, int n_in,
                              void* d_out, int out_size) {
    const float* x    = (const float*)d_in[0];   // [50000,128] f32
    const int*   ei   = (const int*)d_in[1];     // [2,800000] int32 (JAX x64 off)
    const float* w    = (const float*)d_in[2];   // [128,128] f32
    const float* bias = (const float*)d_in[3];   // [128] f32
    float* out = (float*)d_out;                  // [50000,128] f32

    (void)in_sizes; (void)n_in; (void)out_size;

    // 1-3: degree + dinv
    deg_init_kernel<<<(NN + 255) / 256, 256>>>();
    deg_count_kernel<<<(EE + 255) / 256, 256>>>(ei);
    dinv_kernel<<<(NN + 255) / 256, 256>>>();

    // 4: hs = (x@W)*dinv, seed out
    gemm_kernel<<<(NN + 31) / 32, 256>>>(x, w, out);

    // 5: per-edge scatter-add (1 warp / edge; 8 edges / 256-thread block)
    {
        long long total_threads = (long long)EE * 32;
        int blocks = (int)((total_threads + 255) / 256);
        scatter_kernel<<<blocks, 256>>>(ei, out);
    }

    // 6: relu(out*dinv + bias)
    finalize_kernel<<<(NN * 32 + 255) / 256, 256>>>(out, bias);
}

// round 4
// speedup vs baseline: 1.5301x; 1.5301x over previous
#include <cuda_runtime.h>
#include <cstdint>

#define NN 50000
#define EE 800000
#define CC 128
#define SCAN_BLOCKS 196   // ceil(50000/256)

// Scratch (static __device__ arrays — allocation-free)
__device__ float g_hs[(size_t)NN * CC];   // hs[j] = (x@W)[j] * dinv[j]
__device__ float g_dinv[NN];
__device__ int   g_deg[NN];               // edge-only in-degree (self excluded)
__device__ int   g_rowptr[NN + 1];
__device__ int   g_tmp[NN];               // per-block exclusive scan
__device__ int   g_bsum[256];             // block sums (padded)
__device__ int   g_bsumx[256];            // exclusive scan of block sums
__device__ int   g_fill[NN];              // fill cursors
__device__ int   g_srcidx[EE];            // CSR column (src) indices

// ---------------------------------------------------------------------------
// 1) zero edge-degree
__global__ void deg_init_kernel() {
    int i = blockIdx.x * blockDim.x + threadIdx.x;
    if (i < NN) g_deg[i] = 0;
}

// 2) histogram at dst
__global__ void deg_count_kernel(const int* __restrict__ ei) {
    int e = blockIdx.x * blockDim.x + threadIdx.x;
    if (e < EE) atomicAdd(&g_deg[ei[EE + e]], 1);
}

// 3a) per-block exclusive scan of deg
__global__ void scan1_kernel() {
    __shared__ int s[256];
    int t = threadIdx.x;
    int i = blockIdx.x * 256 + t;
    int val = (i < NN) ? g_deg[i] : 0;
    s[t] = val;
    __syncthreads();
#pragma unroll
    for (int off = 1; off < 256; off <<= 1) {
        int v = (t >= off) ? s[t - off] : 0;
        __syncthreads();
        s[t] += v;
        __syncthreads();
    }
    if (i < NN) g_tmp[i] = s[t] - val;       // exclusive
    if (t == 255) g_bsum[blockIdx.x] = s[255];
}

// 3b) scan the block sums (single block)
__global__ void scan2_kernel() {
    __shared__ int s[256];
    int t = threadIdx.x;
    int val = (t < SCAN_BLOCKS) ? g_bsum[t] : 0;
    s[t] = val;
    __syncthreads();
#pragma unroll
    for (int off = 1; off < 256; off <<= 1) {
        int v = (t >= off) ? s[t - off] : 0;
        __syncthreads();
        s[t] += v;
        __syncthreads();
    }
    g_bsumx[t] = s[t] - val;
}

// 3c) finalize row_ptr, zero fill cursors, compute dinv (deg includes +1 self)
__global__ void scan3_kernel() {
    int i = blockIdx.x * blockDim.x + threadIdx.x;
    if (i < NN) {
        g_rowptr[i] = g_tmp[i] + g_bsumx[i >> 8];
        g_fill[i] = 0;
        g_dinv[i] = rsqrtf((float)(g_deg[i] + 1));
    }
    if (i == 0) g_rowptr[NN] = EE;
}

// 4) bucket edges into CSR (order within bucket irrelevant)
__global__ void fill_kernel(const int* __restrict__ ei) {
    int e = blockIdx.x * blockDim.x + threadIdx.x;
    if (e < EE) {
        int src = ei[e];
        int dst = ei[EE + e];
        int pos = atomicAdd(&g_fill[dst], 1);
        g_srcidx[g_rowptr[dst] + pos] = src;
    }
}

// ---------------------------------------------------------------------------
// 5) GEMM: hs = (x @ W) * dinv[row].
//    256 threads, 64 rows/block. Thread = 8 rows (warp-group) x 4 cols (lane).
//    k unrolled by 4: 4 W LDG.128 + 8 x LDS.128 per step, 128 FFMA.
__global__ void gemm_kernel(const float* __restrict__ x,
                            const float* __restrict__ w) {
    __shared__ float4 sx[64][32];   // 32 KB
    const int row0 = blockIdx.x * 64;
    const int t = threadIdx.x;
    const int lane = t & 31;
    const int wg = t >> 5;          // 8 warps
    const int r0 = wg * 8;

    const float4* x4 = (const float4*)x;
    for (int i = t; i < 64 * 32; i += 256) {
        int r = i >> 5, c = i & 31;
        int row = row0 + r;
        sx[r][c] = (row < NN) ? x4[(size_t)row * 32 + c]
                              : make_float4(0.f, 0.f, 0.f, 0.f);
    }
    __syncthreads();

    float acc[8][4] = {};
    const float4* w4 = (const float4*)w;

#pragma unroll 2
    for (int k4 = 0; k4 < 32; k4++) {
        float4 wv0 = w4[(k4 * 4 + 0) * 32 + lane];
        float4 wv1 = w4[(k4 * 4 + 1) * 32 + lane];
        float4 wv2 = w4[(k4 * 4 + 2) * 32 + lane];
        float4 wv3 = w4[(k4 * 4 + 3) * 32 + lane];
#pragma unroll
        for (int r = 0; r < 8; r++) {
            float4 xv = sx[r0 + r][k4];  // broadcast, conflict-free
            acc[r][0] += xv.x * wv0.x; acc[r][1] += xv.x * wv0.y;
            acc[r][2] += xv.x * wv0.z; acc[r][3] += xv.x * wv0.w;
            acc[r][0] += xv.y * wv1.x; acc[r][1] += xv.y * wv1.y;
            acc[r][2] += xv.y * wv1.z; acc[r][3] += xv.y * wv1.w;
            acc[r][0] += xv.z * wv2.x; acc[r][1] += xv.z * wv2.y;
            acc[r][2] += xv.z * wv2.z; acc[r][3] += xv.z * wv2.w;
            acc[r][0] += xv.w * wv3.x; acc[r][1] += xv.w * wv3.y;
            acc[r][2] += xv.w * wv3.z; acc[r][3] += xv.w * wv3.w;
        }
    }

    float4* hs4 = (float4*)g_hs;
#pragma unroll
    for (int r = 0; r < 8; r++) {
        int row = row0 + r0 + r;
        if (row < NN) {
            float d = g_dinv[row];
            hs4[(size_t)row * 32 + lane] =
                make_float4(acc[r][0] * d, acc[r][1] * d,
                            acc[r][2] * d, acc[r][3] * d);
        }
    }
}

// ---------------------------------------------------------------------------
// 6) CSR gather: one warp per node. Accumulate self + in-neighbors' hs rows
//    in registers, single write of relu(acc*dinv + bias). No atomics.
__global__ void gather_kernel(float* __restrict__ out,
                              const float* __restrict__ bias) {
    int warp = (blockIdx.x * blockDim.x + threadIdx.x) >> 5;
    if (warp >= NN) return;
    int lane = threadIdx.x & 31;
    const float4* hs4 = (const float4*)g_hs;

    int start = g_rowptr[warp];
    int end   = g_rowptr[warp + 1];

    float4 acc = __ldg(&hs4[(size_t)warp * 32 + lane]);  // self-loop message

    for (int c = start; c < end; c += 32) {
        int n = min(32, end - c);
        int myidx = (c + lane < end) ? __ldg(&g_srcidx[c + lane]) : 0;
#pragma unroll 4
        for (int j = 0; j < n; j++) {
            int s = __shfl_sync(0xffffffffu, myidx, j);
            float4 v = __ldg(&hs4[(size_t)s * 32 + lane]);
            acc.x += v.x; acc.y += v.y; acc.z += v.z; acc.w += v.w;
        }
    }

    float d = g_dinv[warp];
    float4 b = ((const float4*)bias)[lane];
    float4 o;
    o.x = fmaxf(fmaf(acc.x, d, b.x), 0.f);
    o.y = fmaxf(fmaf(acc.y, d, b.y), 0.f);
    o.z = fmaxf(fmaf(acc.z, d, b.z), 0.f);
    o.w = fmaxf(fmaf(acc.w, d, b.w), 0.f);
    ((float4*)out)[(size_t)warp * 32 + lane] = o;
}

// ---------------------------------------------------------------------------
extern "C" void kernel_launch(void* const* d_in, const int* in_sizes, int n_in,
                              void* d_out, int out_size) {
    const float* x    = (const float*)d_in[0];   // [50000,128] f32
    const int*   ei   = (const int*)d_in[1];     // [2,800000] int32
    const float* w    = (const float*)d_in[2];   // [128,128] f32
    const float* bias = (const float*)d_in[3];   // [128] f32
    float* out = (float*)d_out;                  // [50000,128] f32
    (void)in_sizes; (void)n_in; (void)out_size;

    deg_init_kernel<<<(NN + 255) / 256, 256>>>();
    deg_count_kernel<<<(EE + 255) / 256, 256>>>(ei);
    scan1_kernel<<<SCAN_BLOCKS, 256>>>();
    scan2_kernel<<<1, 256>>>();
    scan3_kernel<<<(NN + 255) / 256, 256>>>();
    fill_kernel<<<(EE + 255) / 256, 256>>>(ei);

    gemm_kernel<<<(NN + 63) / 64, 256>>>(x, w);

    // one warp per node
    gather_kernel<<<(NN * 32 + 255) / 256, 256>>>(out, bias);
}